// round 1
// baseline (speedup 1.0000x reference)
#include <cuda_runtime.h>
#include <math.h>

#define NNODE  50000
#define VOCAB  401
#define MAXH   1000
#define NPAIR  (VOCAB*MAXH)
#define NQ     512
#define NEDGE_DEF 800000

// ---- device scratch (static globals: no runtime allocation allowed) ----
__device__ float d_TrelW1[VOCAB*128];   // rela_embed @ W1[0:128]
__device__ float d_TtimW1[MAXH*128];    // pe @ W1[128:160]
__device__ float d_Tqr[NQ*64];          // rela_embed[q_rel] @ Wqr
__device__ float d_HSWS[NNODE*64];      // hidden @ Ws
__device__ float d_HR[NPAIR*128];       // hr per (rel,tim) pair
__device__ float d_GA[NPAIR*64];        // hr @ Wr per pair
__device__ float d_UP[NNODE*128];
__device__ float d_BOT[NNODE];

typedef unsigned long long u64;
__device__ __forceinline__ u64 pk2(float x, float y){ u64 r; asm("mov.b64 %0,{%1,%2};":"=l"(r):"f"(x),"f"(y)); return r; }
__device__ __forceinline__ void upk2(u64 v, float&x, float&y){ asm("mov.b64 {%0,%1},%2;":"=f"(x),"=f"(y):"l"(v)); }
__device__ __forceinline__ void fma2(u64&d, u64 a, u64 b){ asm("fma.rn.f32x2 %0,%1,%2,%0;":"+l"(d):"l"(a),"l"(b)); }
__device__ __forceinline__ float lrelu(float x){ return x>0.f ? x : 0.01f*x; }

// ---- zero accumulators (must run every launch: graph replays) ----
__global__ void kZero(){
    int i = blockIdx.x*blockDim.x+threadIdx.x;
    int st = gridDim.x*blockDim.x;
    for (int j=i;j<NNODE*128;j+=st) d_UP[j]=0.f;
    for (int j=i;j<NNODE;j+=st)     d_BOT[j]=0.f;
}

// ---- small tables ----
__global__ void kA_rel(const float* __restrict__ rela, const float* __restrict__ W1){
    __shared__ float s[128];
    int b=blockIdx.x, t=threadIdx.x;
    s[t]=rela[b*128+t];
    __syncthreads();
    float acc=0.f;
    #pragma unroll 8
    for(int i=0;i<128;i++) acc += s[i]*W1[i*128+t];
    d_TrelW1[b*128+t]=acc;
}

__global__ void kA_tim(const float* __restrict__ pe, const float* __restrict__ W1){
    __shared__ float s[32];
    int b=blockIdx.x, t=threadIdx.x;
    if(t<32) s[t]=pe[b*32+t];
    __syncthreads();
    float acc=0.f;
    #pragma unroll
    for(int i=0;i<32;i++) acc += s[i]*W1[(128+i)*128+t];
    d_TtimW1[b*128+t]=acc;
}

__global__ void kA_qr(const float* __restrict__ rela, const float* __restrict__ Wqr,
                      const int* __restrict__ q_rel){
    __shared__ float s[128];
    int b=blockIdx.x, t=threadIdx.x;          // 64 threads
    int rel=q_rel[b];
    s[t]     = rela[rel*128+t];
    s[t+64]  = rela[rel*128+t+64];
    __syncthreads();
    float acc=0.f;
    #pragma unroll 8
    for(int i=0;i<128;i++) acc += s[i]*Wqr[i*64+t];
    d_Tqr[b*64+t]=acc;
}

// ---- hidden @ Ws -> HSWS [NNODE,64] ----
__global__ __launch_bounds__(256) void kB(const float* __restrict__ hidden, const float* __restrict__ Ws){
    __shared__ float sW[128*64];
    __shared__ float sX[8][128];
    for(int i=threadIdx.x;i<128*64;i+=256) sW[i]=Ws[i];
    __syncthreads();
    int warp=threadIdx.x>>5, lane=threadIdx.x&31;
    int m0=lane*2;
    for(int n=blockIdx.x*8+warp; n<NNODE; n+=gridDim.x*8){
        *(float4*)&sX[warp][lane*4] = *(const float4*)&hidden[n*128+lane*4];
        __syncwarp();
        u64 acc=0ULL;
        #pragma unroll 16
        for(int j=0;j<128;j++){
            float v=sX[warp][j];
            u64 hv=pk2(v,v);
            u64 w=*(const u64*)&sW[j*64+m0];
            fma2(acc,hv,w);
        }
        float2 r; upk2(acc,r.x,r.y);
        *(float2*)&d_HSWS[n*64+m0]=r;
        __syncwarp();
    }
}

// ---- pair tables: HR[p]=lrelu(lrelu(h1)@W2+b2)+rel_e ; GA[p]=HR[p]@Wr ----
__global__ __launch_bounds__(256) void kC(const float* __restrict__ rela, const float* __restrict__ W2,
                                          const float* __restrict__ b1v, const float* __restrict__ b2v,
                                          const float* __restrict__ Wr){
    extern __shared__ float sm[];
    float* sW2 = sm;                 // 128*128
    float* sWr = sm + 128*128;       // 128*64
    float* sH  = sWr + 128*64;       // 8 warps * 128
    for(int i=threadIdx.x;i<128*128;i+=256) sW2[i]=W2[i];
    for(int i=threadIdx.x;i<128*64;i+=256)  sWr[i]=Wr[i];
    __syncthreads();
    int warp=threadIdx.x>>5, lane=threadIdx.x&31;
    float* h1 = sH + warp*128;
    int k0=lane*4, m0=lane*2;
    for(int p=blockIdx.x*8+warp; p<NPAIR; p+=gridDim.x*8){
        int rel=p/MAXH, tim=p-rel*MAXH;
        float4 a=*(const float4*)&d_TrelW1[rel*128+k0];
        float4 b=*(const float4*)&d_TtimW1[tim*128+k0];
        float4 c=*(const float4*)&b1v[k0];
        float4 hh;
        hh.x=lrelu(a.x+b.x+c.x); hh.y=lrelu(a.y+b.y+c.y);
        hh.z=lrelu(a.z+b.z+c.z); hh.w=lrelu(a.w+b.w+c.w);
        *(float4*)&h1[k0]=hh;
        __syncwarp();
        u64 a01=0ULL, a23=0ULL;
        #pragma unroll 16
        for(int j=0;j<128;j++){
            float v=h1[j];
            u64 hv=pk2(v,v);
            ulonglong2 w=*(const ulonglong2*)&sW2[j*128+k0];
            fma2(a01,hv,w.x); fma2(a23,hv,w.y);
        }
        float h20,h21,h22,h23;
        upk2(a01,h20,h21); upk2(a23,h22,h23);
        float4 bb=*(const float4*)&b2v[k0];
        float4 re=*(const float4*)&rela[rel*128+k0];
        float4 hr;
        hr.x=lrelu(h20+bb.x)+re.x; hr.y=lrelu(h21+bb.y)+re.y;
        hr.z=lrelu(h22+bb.z)+re.z; hr.w=lrelu(h23+bb.w)+re.w;
        *(float4*)&d_HR[p*128+k0]=hr;
        __syncwarp();
        *(float4*)&h1[k0]=hr;
        __syncwarp();
        u64 acc=0ULL;
        #pragma unroll 16
        for(int j=0;j<128;j++){
            float v=h1[j];
            u64 hv=pk2(v,v);
            u64 w=*(const u64*)&sWr[j*64+m0];
            fma2(acc,hv,w);
        }
        float2 g; upk2(acc,g.x,g.y);
        *(float2*)&d_GA[p*64+m0]=g;
        __syncwarp();
    }
}

// ---- per-edge: alpha, exp, scatter-add ----
__global__ __launch_bounds__(256) void kD(const int* __restrict__ edges, const float* __restrict__ hidden,
                                          const float* __restrict__ bqr, const float* __restrict__ w_alpha,
                                          int nedge){
    int e_id=(blockIdx.x*blockDim.x+threadIdx.x)>>5;
    int lane=threadIdx.x&31;
    if(e_id>=nedge) return;
    const int* e = edges + (size_t)e_id*7;
    int r_idx=__ldg(e+0), rel=__ldg(e+2), sub=__ldg(e+4), obj=__ldg(e+5), tim=__ldg(e+6);
    int p = rel*MAXH + tim;
    int m0=lane*2;
    float2 g1=*(const float2*)&d_HSWS[sub*64+m0];
    float2 g2=*(const float2*)&d_GA[p*64+m0];
    float2 g3=*(const float2*)&d_Tqr[r_idx*64+m0];
    float b0=__ldg(&bqr[m0]), b1=__ldg(&bqr[m0+1]);
    float wa0=__ldg(&w_alpha[m0]), wa1=__ldg(&w_alpha[m0+1]);
    float s = lrelu(g1.x+g2.x+g3.x+b0)*wa0 + lrelu(g1.y+g2.y+g3.y+b1)*wa1;
    #pragma unroll
    for(int o=16;o;o>>=1) s += __shfl_xor_sync(0xffffffffu,s,o);
    float ea=expf(s);
    int k0=lane*4;
    float4 hs=*(const float4*)&hidden[(size_t)sub*128+k0];
    float4 hr=*(const float4*)&d_HR[p*128+k0];
    float4 m;
    m.x=ea*(hs.x+hr.x); m.y=ea*(hs.y+hr.y); m.z=ea*(hs.z+hr.z); m.w=ea*(hs.w+hr.w);
    float* up=&d_UP[obj*128+k0];
    asm volatile("red.global.add.v4.f32 [%0], {%1,%2,%3,%4};"
                 :: "l"(up),"f"(m.x),"f"(m.y),"f"(m.z),"f"(m.w) : "memory");
    if(lane==0) atomicAdd(&d_BOT[obj], ea);
}

// ---- final: out = (UP/BOT) @ Wh ----
__global__ __launch_bounds__(256) void kE(const float* __restrict__ Wh, float* __restrict__ out){
    extern __shared__ float sm[];
    float* sW=sm; float* sX=sm+128*128;
    for(int i=threadIdx.x;i<128*128;i+=256) sW[i]=Wh[i];
    __syncthreads();
    int warp=threadIdx.x>>5, lane=threadIdx.x&31;
    float* x=sX+warp*128;
    int k0=lane*4;
    for(int n=blockIdx.x*8+warp; n<NNODE; n+=gridDim.x*8){
        float inv=1.f/(d_BOT[n]+1e-5f);
        float4 u=*(const float4*)&d_UP[n*128+k0];
        float4 xx; xx.x=u.x*inv; xx.y=u.y*inv; xx.z=u.z*inv; xx.w=u.w*inv;
        *(float4*)&x[k0]=xx;
        __syncwarp();
        u64 a01=0ULL, a23=0ULL;
        #pragma unroll 16
        for(int j=0;j<128;j++){
            float v=x[j];
            u64 hv=pk2(v,v);
            ulonglong2 w=*(const ulonglong2*)&sW[j*128+k0];
            fma2(a01,hv,w.x); fma2(a23,hv,w.y);
        }
        float4 r; upk2(a01,r.x,r.y); upk2(a23,r.z,r.w);
        *(float4*)&out[(size_t)n*128+k0]=r;
        __syncwarp();
    }
}

extern "C" void kernel_launch(void* const* d_in, const int* in_sizes, int n_in,
                              void* d_out, int out_size){
    const float* hidden =(const float*)d_in[0];
    const float* rela   =(const float*)d_in[1];
    const float* pe     =(const float*)d_in[2];
    const float* W1     =(const float*)d_in[3];
    const float* b1     =(const float*)d_in[4];
    const float* W2     =(const float*)d_in[5];
    const float* b2     =(const float*)d_in[6];
    const float* Ws     =(const float*)d_in[7];
    const float* Wr     =(const float*)d_in[8];
    const float* Wqr    =(const float*)d_in[9];
    const float* bqr    =(const float*)d_in[10];
    const float* w_alpha=(const float*)d_in[11];
    const float* Wh     =(const float*)d_in[12];
    const int*   q_rel  =(const int*)d_in[13];
    const int*   edges  =(const int*)d_in[14];
    float* out=(float*)d_out;
    int nedge = in_sizes[14]/7;

    int smemC = (128*128 + 128*64 + 8*128)*(int)sizeof(float);
    int smemE = (128*128 + 8*128)*(int)sizeof(float);
    cudaFuncSetAttribute(kC, cudaFuncAttributeMaxDynamicSharedMemorySize, smemC);
    cudaFuncSetAttribute(kE, cudaFuncAttributeMaxDynamicSharedMemorySize, smemE);

    kZero<<<512,256>>>();
    kA_rel<<<VOCAB,128>>>(rela,W1);
    kA_tim<<<MAXH,128>>>(pe,W1);
    kA_qr<<<NQ,64>>>(rela,Wqr,q_rel);
    kB<<<296,256>>>(hidden,Ws);
    kC<<<296,256,smemC>>>(rela,W2,b1,b2,Wr);
    kD<<<(nedge*32+255)/256,256>>>(edges,hidden,bqr,w_alpha,nedge);
    kE<<<296,256,smemE>>>(Wh,out);
}

// round 2
// speedup vs baseline: 1.8435x; 1.8435x over previous
#include <cuda_runtime.h>
#include <math.h>

#define NNODE  50000
#define VOCAB  401
#define MAXH   1000
#define NPAIR  (VOCAB*MAXH)
#define NQ     512

// ---- device scratch ----
__device__ float d_TrelW1[VOCAB*128];
__device__ float d_TtimW1[MAXH*128];
__device__ float d_Tqr[NQ*64];
__device__ float d_HSWS[NNODE*64];
__device__ float d_HR[NPAIR*128];
__device__ float d_GA[NPAIR*64];
__device__ float d_UP[NNODE*128];
__device__ float d_BOT[NNODE];

typedef unsigned long long u64;
__device__ __forceinline__ u64 pk2(float x, float y){ u64 r; asm("mov.b64 %0,{%1,%2};":"=l"(r):"f"(x),"f"(y)); return r; }
__device__ __forceinline__ void upk2(u64 v, float&x, float&y){ asm("mov.b64 {%0,%1},%2;":"=f"(x),"=f"(y):"l"(v)); }
__device__ __forceinline__ void fma2(u64&d, u64 a, u64 b){ asm("fma.rn.f32x2 %0,%1,%2,%0;":"+l"(d):"l"(a),"l"(b)); }
__device__ __forceinline__ float lrelu(float x){ return x>0.f ? x : 0.01f*x; }

__global__ void kZero(){
    int i = blockIdx.x*blockDim.x+threadIdx.x;
    int st = gridDim.x*blockDim.x;
    for (int j=i;j<NNODE*128;j+=st) d_UP[j]=0.f;
    for (int j=i;j<NNODE;j+=st)     d_BOT[j]=0.f;
}

__global__ void kA_rel(const float* __restrict__ rela, const float* __restrict__ W1){
    __shared__ float s[128];
    int b=blockIdx.x, t=threadIdx.x;
    s[t]=rela[b*128+t];
    __syncthreads();
    float acc=0.f;
    #pragma unroll 8
    for(int i=0;i<128;i++) acc += s[i]*W1[i*128+t];
    d_TrelW1[b*128+t]=acc;
}

__global__ void kA_tim(const float* __restrict__ pe, const float* __restrict__ W1){
    __shared__ float s[32];
    int b=blockIdx.x, t=threadIdx.x;
    if(t<32) s[t]=pe[b*32+t];
    __syncthreads();
    float acc=0.f;
    #pragma unroll
    for(int i=0;i<32;i++) acc += s[i]*W1[(128+i)*128+t];
    d_TtimW1[b*128+t]=acc;
}

__global__ void kA_qr(const float* __restrict__ rela, const float* __restrict__ Wqr,
                      const int* __restrict__ q_rel){
    __shared__ float s[128];
    int b=blockIdx.x, t=threadIdx.x;          // 64 threads
    int rel=q_rel[b];
    s[t]     = rela[rel*128+t];
    s[t+64]  = rela[rel*128+t+64];
    __syncthreads();
    float acc=0.f;
    #pragma unroll 8
    for(int i=0;i<128;i++) acc += s[i]*Wqr[i*64+t];
    d_Tqr[b*64+t]=acc;
}

__global__ __launch_bounds__(256) void kB(const float* __restrict__ hidden, const float* __restrict__ Ws){
    __shared__ float sW[128*64];
    __shared__ float sX[8][128];
    for(int i=threadIdx.x;i<128*64;i+=256) sW[i]=Ws[i];
    __syncthreads();
    int warp=threadIdx.x>>5, lane=threadIdx.x&31;
    int m0=lane*2;
    for(int n=blockIdx.x*8+warp; n<NNODE; n+=gridDim.x*8){
        *(float4*)&sX[warp][lane*4] = *(const float4*)&hidden[n*128+lane*4];
        __syncwarp();
        u64 acc=0ULL;
        #pragma unroll 16
        for(int j=0;j<128;j++){
            float v=sX[warp][j];
            u64 hv=pk2(v,v);
            u64 w=*(const u64*)&sW[j*64+m0];
            fma2(acc,hv,w);
        }
        float2 r; upk2(acc,r.x,r.y);
        *(float2*)&d_HSWS[n*64+m0]=r;
        __syncwarp();
    }
}

// ---- pair tables, 4 pairs per warp (weight reuse -> FMA-bound) ----
#define KC_WARPS 16
__global__ __launch_bounds__(512) void kC(const float* __restrict__ rela, const float* __restrict__ W2,
                                          const float* __restrict__ b1v, const float* __restrict__ b2v,
                                          const float* __restrict__ Wr){
    extern __shared__ float sm[];
    float* sW2 = sm;                       // 128*128
    float* sWr = sm + 128*128;             // 128*64
    float* sH  = sWr + 128*64;             // KC_WARPS * 4 * 128
    for(int i=threadIdx.x;i<128*128;i+=512) sW2[i]=W2[i];
    for(int i=threadIdx.x;i<128*64;i+=512)  sWr[i]=Wr[i];
    __syncthreads();
    int warp=threadIdx.x>>5, lane=threadIdx.x&31;
    float* h = sH + warp*4*128;            // h[p*128+j]
    int k0=lane*4, m0=lane*2;
    const int ngroup = NPAIR/4;            // 100250, exact

    for(int g=blockIdx.x*KC_WARPS+warp; g<ngroup; g+=gridDim.x*KC_WARPS){
        int pbase = g*4;
        int relv[4], timv[4];
        // phase A: h1 for 4 pairs
        float4 c4=*(const float4*)&b1v[k0];
        #pragma unroll
        for(int p=0;p<4;p++){
            int pp=pbase+p;
            int rel=pp/MAXH, tim=pp-rel*MAXH;
            relv[p]=rel; timv[p]=tim;
            float4 a=*(const float4*)&d_TrelW1[rel*128+k0];
            float4 b=*(const float4*)&d_TtimW1[tim*128+k0];
            float4 hh;
            hh.x=lrelu(a.x+b.x+c4.x); hh.y=lrelu(a.y+b.y+c4.y);
            hh.z=lrelu(a.z+b.z+c4.z); hh.w=lrelu(a.w+b.w+c4.w);
            *(float4*)&h[p*128+k0]=hh;
        }
        __syncwarp();
        // GEMM1: h1 @ W2 (4 pairs share each weight row)
        u64 a01[4]={0,0,0,0}, a23[4]={0,0,0,0};
        #pragma unroll 4
        for(int j=0;j<128;j+=4){
            float4 hp0=*(const float4*)&h[0*128+j];
            float4 hp1=*(const float4*)&h[1*128+j];
            float4 hp2=*(const float4*)&h[2*128+j];
            float4 hp3=*(const float4*)&h[3*128+j];
            float hv[4][4]={{hp0.x,hp0.y,hp0.z,hp0.w},{hp1.x,hp1.y,hp1.z,hp1.w},
                            {hp2.x,hp2.y,hp2.z,hp2.w},{hp3.x,hp3.y,hp3.z,hp3.w}};
            #pragma unroll
            for(int jj=0;jj<4;jj++){
                ulonglong2 w=*(const ulonglong2*)&sW2[(j+jj)*128+k0];
                #pragma unroll
                for(int p=0;p<4;p++){
                    u64 hb=pk2(hv[p][jj],hv[p][jj]);
                    fma2(a01[p],hb,w.x); fma2(a23[p],hb,w.y);
                }
            }
        }
        __syncwarp();
        // epilogue: hr = lrelu(h2+b2)+rel_e ; write HR ; stash hr in sH
        float4 bb=*(const float4*)&b2v[k0];
        #pragma unroll
        for(int p=0;p<4;p++){
            float h0,h1f,h2,h3;
            upk2(a01[p],h0,h1f); upk2(a23[p],h2,h3);
            float4 re=*(const float4*)&rela[relv[p]*128+k0];
            float4 hr;
            hr.x=lrelu(h0+bb.x)+re.x; hr.y=lrelu(h1f+bb.y)+re.y;
            hr.z=lrelu(h2+bb.z)+re.z; hr.w=lrelu(h3+bb.w)+re.w;
            *(float4*)&d_HR[(size_t)(pbase+p)*128+k0]=hr;
            *(float4*)&h[p*128+k0]=hr;
        }
        __syncwarp();
        // GEMM2: hr @ Wr
        u64 gacc[4]={0,0,0,0};
        #pragma unroll 4
        for(int j=0;j<128;j+=4){
            float4 hp0=*(const float4*)&h[0*128+j];
            float4 hp1=*(const float4*)&h[1*128+j];
            float4 hp2=*(const float4*)&h[2*128+j];
            float4 hp3=*(const float4*)&h[3*128+j];
            float hv[4][4]={{hp0.x,hp0.y,hp0.z,hp0.w},{hp1.x,hp1.y,hp1.z,hp1.w},
                            {hp2.x,hp2.y,hp2.z,hp2.w},{hp3.x,hp3.y,hp3.z,hp3.w}};
            #pragma unroll
            for(int jj=0;jj<4;jj++){
                u64 w=*(const u64*)&sWr[(j+jj)*64+m0];
                #pragma unroll
                for(int p=0;p<4;p++){
                    u64 hb=pk2(hv[p][jj],hv[p][jj]);
                    fma2(gacc[p],hb,w);
                }
            }
        }
        #pragma unroll
        for(int p=0;p<4;p++){
            float2 gv; upk2(gacc[p],gv.x,gv.y);
            *(float2*)&d_GA[(size_t)(pbase+p)*64+m0]=gv;
        }
        __syncwarp();
    }
}

// ---- per-edge: alpha, exp, scatter-add ----
__global__ __launch_bounds__(256) void kD(const int* __restrict__ edges, const float* __restrict__ hidden,
                                          const float* __restrict__ bqr, const float* __restrict__ w_alpha,
                                          int nedge){
    int e_id=(blockIdx.x*blockDim.x+threadIdx.x)>>5;
    int lane=threadIdx.x&31;
    if(e_id>=nedge) return;
    const int* e = edges + (size_t)e_id*7;
    int r_idx=__ldg(e+0), rel=__ldg(e+2), sub=__ldg(e+4), obj=__ldg(e+5), tim=__ldg(e+6);
    int p = rel*MAXH + tim;
    int m0=lane*2;
    float2 g1=*(const float2*)&d_HSWS[sub*64+m0];
    float2 g2=*(const float2*)&d_GA[(size_t)p*64+m0];
    float2 g3=*(const float2*)&d_Tqr[r_idx*64+m0];
    float b0=__ldg(&bqr[m0]), b1=__ldg(&bqr[m0+1]);
    float wa0=__ldg(&w_alpha[m0]), wa1=__ldg(&w_alpha[m0+1]);
    float s = lrelu(g1.x+g2.x+g3.x+b0)*wa0 + lrelu(g1.y+g2.y+g3.y+b1)*wa1;
    #pragma unroll
    for(int o=16;o;o>>=1) s += __shfl_xor_sync(0xffffffffu,s,o);
    float ea=expf(s);
    int k0=lane*4;
    float4 hs=*(const float4*)&hidden[(size_t)sub*128+k0];
    float4 hr=*(const float4*)&d_HR[(size_t)p*128+k0];
    float4 m;
    m.x=ea*(hs.x+hr.x); m.y=ea*(hs.y+hr.y); m.z=ea*(hs.z+hr.z); m.w=ea*(hs.w+hr.w);
    float* up=&d_UP[obj*128+k0];
    asm volatile("red.global.add.v4.f32 [%0], {%1,%2,%3,%4};"
                 :: "l"(up),"f"(m.x),"f"(m.y),"f"(m.z),"f"(m.w) : "memory");
    if(lane==0) atomicAdd(&d_BOT[obj], ea);
}

// ---- final: out = (UP/BOT) @ Wh ----
__global__ __launch_bounds__(256) void kE(const float* __restrict__ Wh, float* __restrict__ out){
    extern __shared__ float sm[];
    float* sW=sm; float* sX=sm+128*128;
    for(int i=threadIdx.x;i<128*128;i+=256) sW[i]=Wh[i];
    __syncthreads();
    int warp=threadIdx.x>>5, lane=threadIdx.x&31;
    float* x=sX+warp*128;
    int k0=lane*4;
    for(int n=blockIdx.x*8+warp; n<NNODE; n+=gridDim.x*8){
        float inv=1.f/(d_BOT[n]+1e-5f);
        float4 u=*(const float4*)&d_UP[n*128+k0];
        float4 xx; xx.x=u.x*inv; xx.y=u.y*inv; xx.z=u.z*inv; xx.w=u.w*inv;
        *(float4*)&x[k0]=xx;
        __syncwarp();
        u64 a01=0ULL, a23=0ULL;
        #pragma unroll 16
        for(int j=0;j<128;j++){
            float v=x[j];
            u64 hv=pk2(v,v);
            ulonglong2 w=*(const ulonglong2*)&sW[j*128+k0];
            fma2(a01,hv,w.x); fma2(a23,hv,w.y);
        }
        float4 r; upk2(a01,r.x,r.y); upk2(a23,r.z,r.w);
        *(float4*)&out[(size_t)n*128+k0]=r;
        __syncwarp();
    }
}

extern "C" void kernel_launch(void* const* d_in, const int* in_sizes, int n_in,
                              void* d_out, int out_size){
    const float* hidden =(const float*)d_in[0];
    const float* rela   =(const float*)d_in[1];
    const float* pe     =(const float*)d_in[2];
    const float* W1     =(const float*)d_in[3];
    const float* b1     =(const float*)d_in[4];
    const float* W2     =(const float*)d_in[5];
    const float* b2     =(const float*)d_in[6];
    const float* Ws     =(const float*)d_in[7];
    const float* Wr     =(const float*)d_in[8];
    const float* Wqr    =(const float*)d_in[9];
    const float* bqr    =(const float*)d_in[10];
    const float* w_alpha=(const float*)d_in[11];
    const float* Wh     =(const float*)d_in[12];
    const int*   q_rel  =(const int*)d_in[13];
    const int*   edges  =(const int*)d_in[14];
    float* out=(float*)d_out;
    int nedge = in_sizes[14]/7;

    int smemC = (128*128 + 128*64 + KC_WARPS*4*128)*(int)sizeof(float);
    int smemE = (128*128 + 8*128)*(int)sizeof(float);
    cudaFuncSetAttribute(kC, cudaFuncAttributeMaxDynamicSharedMemorySize, smemC);
    cudaFuncSetAttribute(kE, cudaFuncAttributeMaxDynamicSharedMemorySize, smemE);

    kZero<<<512,256>>>();
    kA_rel<<<VOCAB,128>>>(rela,W1);
    kA_tim<<<MAXH,128>>>(pe,W1);
    kA_qr<<<NQ,64>>>(rela,Wqr,q_rel);
    kB<<<296,256>>>(hidden,Ws);
    kC<<<148,512,smemC>>>(rela,W2,b1,b2,Wr);
    kD<<<(nedge*32+255)/256,256>>>(edges,hidden,bqr,w_alpha,nedge);
    kE<<<296,256,smemE>>>(Wh,out);
}

// round 4
// speedup vs baseline: 3.1648x; 1.7168x over previous
#include <cuda_runtime.h>
#include <cuda_bf16.h>
#include <math.h>

#define NNODE  50000
#define VOCAB  401
#define MAXH   1000
#define NPAIR  (VOCAB*MAXH)
#define NQ     512

// ---- device scratch ----
__device__ float d_TrelW1[VOCAB*128];   // rela@W1[0:128] + b1
__device__ float d_TtimW1[MAXH*128];
__device__ float d_Tqr[NQ*64];
__device__ float d_HSWS[NNODE*64];
__device__ float d_HR[NPAIR*128];
__device__ float d_GA[NPAIR*64];
__device__ float d_UP[NNODE*128];
__device__ float d_BOT[NNODE];

typedef unsigned long long u64;
typedef unsigned int u32;
__device__ __forceinline__ u64 pk2(float x, float y){ u64 r; asm("mov.b64 %0,{%1,%2};":"=l"(r):"f"(x),"f"(y)); return r; }
__device__ __forceinline__ void upk2(u64 v, float&x, float&y){ asm("mov.b64 {%0,%1},%2;":"=f"(x),"=f"(y):"l"(v)); }
__device__ __forceinline__ void fma2(u64&d, u64 a, u64 b){ asm("fma.rn.f32x2 %0,%1,%2,%0;":"+l"(d):"l"(a),"l"(b)); }
__device__ __forceinline__ float lrelu(float x){ return x>0.f ? x : 0.01f*x; }
__device__ __forceinline__ u32 bf2(float a, float b){ u32 r; asm("cvt.rn.bf16x2.f32 %0,%2,%1;":"=r"(r):"f"(a),"f"(b)); return r; }
__device__ __forceinline__ u32 s2u(const void* p){ u32 a; asm("{ .reg .u64 t; cvta.to.shared.u64 t,%1; cvt.u32.u64 %0,t; }":"=r"(a):"l"(p)); return a; }

// ===================== simple kernels =====================
__global__ void kZero(){
    int i = blockIdx.x*blockDim.x+threadIdx.x;
    int st = gridDim.x*blockDim.x;
    for (int j=i;j<NNODE*128;j+=st) d_UP[j]=0.f;
    for (int j=i;j<NNODE;j+=st)     d_BOT[j]=0.f;
}

__global__ void kA_rel(const float* __restrict__ rela, const float* __restrict__ W1,
                       const float* __restrict__ b1v){
    __shared__ float s[128];
    int b=blockIdx.x, t=threadIdx.x;
    s[t]=rela[b*128+t];
    __syncthreads();
    float acc=b1v[t];
    #pragma unroll 8
    for(int i=0;i<128;i++) acc += s[i]*W1[i*128+t];
    d_TrelW1[b*128+t]=acc;
}

__global__ void kA_tim(const float* __restrict__ pe, const float* __restrict__ W1){
    __shared__ float s[32];
    int b=blockIdx.x, t=threadIdx.x;
    if(t<32) s[t]=pe[b*32+t];
    __syncthreads();
    float acc=0.f;
    #pragma unroll
    for(int i=0;i<32;i++) acc += s[i]*W1[(128+i)*128+t];
    d_TtimW1[b*128+t]=acc;
}

__global__ void kA_qr(const float* __restrict__ rela, const float* __restrict__ Wqr,
                      const int* __restrict__ q_rel){
    __shared__ float s[128];
    int b=blockIdx.x, t=threadIdx.x;          // 64 threads
    int rel=q_rel[b];
    s[t]     = rela[rel*128+t];
    s[t+64]  = rela[rel*128+t+64];
    __syncthreads();
    float acc=0.f;
    #pragma unroll 8
    for(int i=0;i<128;i++) acc += s[i]*Wqr[i*64+t];
    d_Tqr[b*64+t]=acc;
}

__global__ __launch_bounds__(256) void kB(const float* __restrict__ hidden, const float* __restrict__ Ws){
    __shared__ float sW[128*64];
    __shared__ float sX[8][128];
    for(int i=threadIdx.x;i<128*64;i+=256) sW[i]=Ws[i];
    __syncthreads();
    int warp=threadIdx.x>>5, lane=threadIdx.x&31;
    int m0=lane*2;
    for(int n=blockIdx.x*8+warp; n<NNODE; n+=gridDim.x*8){
        *(float4*)&sX[warp][lane*4] = *(const float4*)&hidden[n*128+lane*4];
        __syncwarp();
        u64 acc=0ULL;
        #pragma unroll 16
        for(int j=0;j<128;j++){
            float v=sX[warp][j];
            u64 hv=pk2(v,v);
            u64 w=*(const u64*)&sW[j*64+m0];
            fma2(acc,hv,w);
        }
        float2 r; upk2(acc,r.x,r.y);
        *(float2*)&d_HSWS[n*64+m0]=r;
        __syncwarp();
    }
}

// ===================== mma.sync pair kernel =====================
#define SAS 136   // smem stride in bf16 elems (272B: ldmatrix bank-safe)
// smem bytes: sW2 128*SAS*2=34816 | sWr 64*SAS*2=17408 | sB2 512 | sA 8*16*SAS*2=34816
#define OFF_WR 34816
#define OFF_B2 52224
#define OFF_SA 52736
#define SMEM_C (OFF_SA+34816)

__device__ __forceinline__ void ldm4(u32&r0,u32&r1,u32&r2,u32&r3,u32 addr){
    asm volatile("ldmatrix.sync.aligned.m8n8.x4.shared.b16 {%0,%1,%2,%3},[%4];"
                 :"=r"(r0),"=r"(r1),"=r"(r2),"=r"(r3):"r"(addr));
}
__device__ __forceinline__ void mma16816(float* c, u32 a0,u32 a1,u32 a2,u32 a3, u32 b0,u32 b1){
    asm volatile("mma.sync.aligned.m16n8k16.row.col.f32.bf16.bf16.f32 "
        "{%0,%1,%2,%3},{%4,%5,%6,%7},{%8,%9},{%0,%1,%2,%3};"
        :"+f"(c[0]),"+f"(c[1]),"+f"(c[2]),"+f"(c[3])
        :"r"(a0),"r"(a1),"r"(a2),"r"(a3),"r"(b0),"r"(b1));
}
__device__ __forceinline__ void sts32(u32 addr, u32 v){ asm volatile("st.shared.b32 [%0],%1;"::"r"(addr),"r"(v):"memory"); }

__global__ __launch_bounds__(256) void kC_mma(const float* __restrict__ rela, const float* __restrict__ W2,
                                              const float* __restrict__ b2v, const float* __restrict__ Wr){
    extern __shared__ char smc[];
    __nv_bfloat16* sW2 = (__nv_bfloat16*)smc;
    __nv_bfloat16* sWr = (__nv_bfloat16*)(smc+OFF_WR);
    float* sB2 = (float*)(smc+OFF_B2);
    int tid=threadIdx.x, warp=tid>>5, lane=tid&31;

    // weights -> smem, K-major bf16 (Bt[n][k])
    {
        int n = tid & 127, kh = tid >> 7;
        for(int k=kh; k<128; k+=2) sW2[n*SAS+k] = __float2bfloat16(W2[k*128+n]);
        int n2 = tid & 63, kh2 = tid >> 6;
        for(int k=kh2; k<128; k+=4) sWr[n2*SAS+k] = __float2bfloat16(Wr[k*64+n2]);
        if(tid<128) sB2[tid] = b2v[tid];
    }
    __syncthreads();

    u32 sAb  = s2u(smc+OFF_SA) + warp*16*SAS*2;
    u32 sW2b = s2u(smc);
    u32 sWrb = s2u(smc+OFF_WR);

    // ldmatrix lane address components
    u32 aAddr = sAb + (u32)(((lane&15)*SAS + (lane>>4)*8)*2);
    u32 bLpart = (u32)((((lane&7) + ((lane>>4)<<3))*SAS + ((lane>>3)&1)*8)*2);

    int rquad = lane>>2, cpair = (lane&3)*2;
    const int ngroup = (NPAIR+15)/16;

    for(int g=blockIdx.x*8+warp; g<ngroup; g+=gridDim.x*8){
        int pb = g*16;
        // ---- build A: h1 = lrelu(TrelW1+TtimW1+b1) bf16, rows warp-private ----
        #pragma unroll 4
        for(int rr=0; rr<16; rr++){
            int p = pb+rr; if(p>NPAIR-1) p=NPAIR-1;
            int rel=p/MAXH, tim=p-rel*MAXH;
            float4 a=*(const float4*)&d_TrelW1[rel*128+lane*4];
            float4 b=*(const float4*)&d_TtimW1[tim*128+lane*4];
            u32 lo=bf2(lrelu(a.x+b.x),lrelu(a.y+b.y));
            u32 hi=bf2(lrelu(a.z+b.z),lrelu(a.w+b.w));
            asm volatile("st.shared.v2.b32 [%0],{%1,%2};"
                         ::"r"(sAb+(u32)((rr*SAS+lane*4)*2)),"r"(lo),"r"(hi):"memory");
        }
        __syncwarp();
        // ---- GEMM1: [16x128] = A @ W2t^T ----
        float c[16][4];
        #pragma unroll
        for(int i=0;i<16;i++){ c[i][0]=0.f;c[i][1]=0.f;c[i][2]=0.f;c[i][3]=0.f; }
        #pragma unroll
        for(int kk=0;kk<8;kk++){
            u32 a0,a1,a2,a3;
            ldm4(a0,a1,a2,a3, aAddr + kk*32);
            #pragma unroll
            for(int np=0;np<8;np++){
                u32 b0,b1,b2r,b3;
                ldm4(b0,b1,b2r,b3, sW2b + bLpart + (u32)(np*16*SAS*2) + kk*32);
                mma16816(c[np*2],   a0,a1,a2,a3, b0,b1);
                mma16816(c[np*2+1], a0,a1,a2,a3, b2r,b3);
            }
        }
        // ---- epilogue1: hr = lrelu(h2+b2)+rel_e -> d_HR (fp32) + sA (bf16) ----
        {
            int p_a = pb + rquad, p_b = p_a + 8;
            int pac = p_a>NPAIR-1?NPAIR-1:p_a, pbc = p_b>NPAIR-1?NPAIR-1:p_b;
            const float* ra = rela + (pac/MAXH)*128;
            const float* rb = rela + (pbc/MAXH)*128;
            bool wa = p_a<NPAIR, wb = p_b<NPAIR;
            #pragma unroll
            for(int nt=0;nt<16;nt++){
                int col = nt*8 + cpair;
                float h0 = lrelu(c[nt][0]+sB2[col])   + __ldg(&ra[col]);
                float h1 = lrelu(c[nt][1]+sB2[col+1]) + __ldg(&ra[col+1]);
                float h2 = lrelu(c[nt][2]+sB2[col])   + __ldg(&rb[col]);
                float h3 = lrelu(c[nt][3]+sB2[col+1]) + __ldg(&rb[col+1]);
                if(wa){ float2 v={h0,h1}; *(float2*)&d_HR[(size_t)p_a*128+col]=v; }
                if(wb){ float2 v={h2,h3}; *(float2*)&d_HR[(size_t)p_b*128+col]=v; }
                sts32(sAb+(u32)((rquad*SAS+col)*2),     bf2(h0,h1));
                sts32(sAb+(u32)(((rquad+8)*SAS+col)*2), bf2(h2,h3));
            }
        }
        __syncwarp();
        // ---- GEMM2: [16x64] = hr @ Wr^T ----
        float c2[8][4];
        #pragma unroll
        for(int i=0;i<8;i++){ c2[i][0]=0.f;c2[i][1]=0.f;c2[i][2]=0.f;c2[i][3]=0.f; }
        #pragma unroll
        for(int kk=0;kk<8;kk++){
            u32 a0,a1,a2,a3;
            ldm4(a0,a1,a2,a3, aAddr + kk*32);
            #pragma unroll
            for(int np=0;np<4;np++){
                u32 b0,b1,b2r,b3;
                ldm4(b0,b1,b2r,b3, sWrb + bLpart + (u32)(np*16*SAS*2) + kk*32);
                mma16816(c2[np*2],   a0,a1,a2,a3, b0,b1);
                mma16816(c2[np*2+1], a0,a1,a2,a3, b2r,b3);
            }
        }
        // ---- epilogue2: GA ----
        {
            int p_a = pb + rquad, p_b = p_a + 8;
            bool wa = p_a<NPAIR, wb = p_b<NPAIR;
            #pragma unroll
            for(int nt=0;nt<8;nt++){
                int col = nt*8 + cpair;
                if(wa){ float2 v={c2[nt][0],c2[nt][1]}; *(float2*)&d_GA[(size_t)p_a*64+col]=v; }
                if(wb){ float2 v={c2[nt][2],c2[nt][3]}; *(float2*)&d_GA[(size_t)p_b*64+col]=v; }
            }
        }
        __syncwarp();
    }
}

// ===================== per-edge kernel (unchanged) =====================
__global__ __launch_bounds__(256) void kD(const int* __restrict__ edges, const float* __restrict__ hidden,
                                          const float* __restrict__ bqr, const float* __restrict__ w_alpha,
                                          int nedge){
    int e_id=(blockIdx.x*blockDim.x+threadIdx.x)>>5;
    int lane=threadIdx.x&31;
    if(e_id>=nedge) return;
    const int* e = edges + (size_t)e_id*7;
    int r_idx=__ldg(e+0), rel=__ldg(e+2), sub=__ldg(e+4), obj=__ldg(e+5), tim=__ldg(e+6);
    int p = rel*MAXH + tim;
    int m0=lane*2;
    float2 g1=*(const float2*)&d_HSWS[sub*64+m0];
    float2 g2=*(const float2*)&d_GA[(size_t)p*64+m0];
    float2 g3=*(const float2*)&d_Tqr[r_idx*64+m0];
    float b0=__ldg(&bqr[m0]), b1=__ldg(&bqr[m0+1]);
    float wa0=__ldg(&w_alpha[m0]), wa1=__ldg(&w_alpha[m0+1]);
    float s = lrelu(g1.x+g2.x+g3.x+b0)*wa0 + lrelu(g1.y+g2.y+g3.y+b1)*wa1;
    #pragma unroll
    for(int o=16;o;o>>=1) s += __shfl_xor_sync(0xffffffffu,s,o);
    float ea=expf(s);
    int k0=lane*4;
    float4 hs=*(const float4*)&hidden[(size_t)sub*128+k0];
    float4 hr=*(const float4*)&d_HR[(size_t)p*128+k0];
    float4 m;
    m.x=ea*(hs.x+hr.x); m.y=ea*(hs.y+hr.y); m.z=ea*(hs.z+hr.z); m.w=ea*(hs.w+hr.w);
    float* up=&d_UP[obj*128+k0];
    asm volatile("red.global.add.v4.f32 [%0], {%1,%2,%3,%4};"
                 :: "l"(up),"f"(m.x),"f"(m.y),"f"(m.z),"f"(m.w) : "memory");
    if(lane==0) atomicAdd(&d_BOT[obj], ea);
}

// ===================== final GEMM (unchanged) =====================
__global__ __launch_bounds__(256) void kE(const float* __restrict__ Wh, float* __restrict__ out){
    extern __shared__ float sm[];
    float* sW=sm; float* sX=sm+128*128;
    for(int i=threadIdx.x;i<128*128;i+=256) sW[i]=Wh[i];
    __syncthreads();
    int warp=threadIdx.x>>5, lane=threadIdx.x&31;
    float* x=sX+warp*128;
    int k0=lane*4;
    for(int n=blockIdx.x*8+warp; n<NNODE; n+=gridDim.x*8){
        float inv=1.f/(d_BOT[n]+1e-5f);
        float4 u=*(const float4*)&d_UP[n*128+k0];
        float4 xx; xx.x=u.x*inv; xx.y=u.y*inv; xx.z=u.z*inv; xx.w=u.w*inv;
        *(float4*)&x[k0]=xx;
        __syncwarp();
        u64 a01=0ULL, a23=0ULL;
        #pragma unroll 16
        for(int j=0;j<128;j++){
            float v=x[j];
            u64 hv=pk2(v,v);
            ulonglong2 w=*(const ulonglong2*)&sW[j*128+k0];
            fma2(a01,hv,w.x); fma2(a23,hv,w.y);
        }
        float4 r; upk2(a01,r.x,r.y); upk2(a23,r.z,r.w);
        *(float4*)&out[(size_t)n*128+k0]=r;
        __syncwarp();
    }
}

extern "C" void kernel_launch(void* const* d_in, const int* in_sizes, int n_in,
                              void* d_out, int out_size){
    const float* hidden =(const float*)d_in[0];
    const float* rela   =(const float*)d_in[1];
    const float* pe     =(const float*)d_in[2];
    const float* W1     =(const float*)d_in[3];
    const float* b1     =(const float*)d_in[4];
    const float* W2     =(const float*)d_in[5];
    const float* b2     =(const float*)d_in[6];
    const float* Ws     =(const float*)d_in[7];
    const float* Wr     =(const float*)d_in[8];
    const float* Wqr    =(const float*)d_in[9];
    const float* bqr    =(const float*)d_in[10];
    const float* w_alpha=(const float*)d_in[11];
    const float* Wh     =(const float*)d_in[12];
    const int*   q_rel  =(const int*)d_in[13];
    const int*   edges  =(const int*)d_in[14];
    float* out=(float*)d_out;
    int nedge = in_sizes[14]/7;

    int smemE = (128*128 + 8*128)*(int)sizeof(float);
    cudaFuncSetAttribute(kC_mma, cudaFuncAttributeMaxDynamicSharedMemorySize, SMEM_C);
    cudaFuncSetAttribute(kE, cudaFuncAttributeMaxDynamicSharedMemorySize, smemE);

    kZero<<<512,256>>>();
    kA_rel<<<VOCAB,128>>>(rela,W1,b1);
    kA_tim<<<MAXH,128>>>(pe,W1);
    kA_qr<<<NQ,64>>>(rela,Wqr,q_rel);
    kB<<<296,256>>>(hidden,Ws);
    kC_mma<<<296,256,SMEM_C>>>(rela,W2,b2,Wr);
    kD<<<(nedge*32+255)/256,256>>>(edges,hidden,bqr,w_alpha,nedge);
    kE<<<296,256,smemE>>>(Wh,out);
}

// round 6
// speedup vs baseline: 3.4035x; 1.0754x over previous
#include <cuda_runtime.h>
#include <cuda_bf16.h>
#include <math.h>

#define NNODE  50000
#define VOCAB  401
#define MAXH   1000
#define NPAIR  (VOCAB*MAXH)
#define NQ     512

// ---- device scratch ----
__device__ float d_TrelW1[VOCAB*128];   // rela@W1[0:128] + b1
__device__ float d_TtimW1[MAXH*128];
__device__ float d_Tqr[NQ*64];          // rela[q_rel]@Wqr + bqr
__device__ float d_HSWS[NNODE*64];
__device__ unsigned int d_HRh[NPAIR*64];   // bf16x2 HR
__device__ unsigned int d_GAh[NPAIR*32];   // bf16x2 GA
__device__ float d_UP[NNODE*128];
__device__ float d_BOT[NNODE];

typedef unsigned long long u64;
typedef unsigned int u32;
__device__ __forceinline__ u64 pk2(float x, float y){ u64 r; asm("mov.b64 %0,{%1,%2};":"=l"(r):"f"(x),"f"(y)); return r; }
__device__ __forceinline__ void upk2(u64 v, float&x, float&y){ asm("mov.b64 {%0,%1},%2;":"=f"(x),"=f"(y):"l"(v)); }
__device__ __forceinline__ void fma2(u64&d, u64 a, u64 b){ asm("fma.rn.f32x2 %0,%1,%2,%0;":"+l"(d):"l"(a),"l"(b)); }
__device__ __forceinline__ float lrelu(float x){ return x>0.f ? x : 0.01f*x; }
__device__ __forceinline__ u32 bf2(float a, float b){ u32 r; asm("cvt.rn.bf16x2.f32 %0,%2,%1;":"=r"(r):"f"(a),"f"(b)); return r; }
__device__ __forceinline__ float2 bf2f(u32 v){ float2 r; r.x=__uint_as_float(v<<16); r.y=__uint_as_float(v&0xffff0000u); return r; }
__device__ __forceinline__ u32 s2u(const void* p){ u32 a; asm("{ .reg .u64 t; cvta.to.shared.u64 t,%1; cvt.u32.u64 %0,t; }":"=r"(a):"l"(p)); return a; }

// ===================== simple kernels =====================
__global__ void kZero(){
    int i = blockIdx.x*blockDim.x+threadIdx.x;
    int st = gridDim.x*blockDim.x;
    for (int j=i;j<NNODE*128;j+=st) d_UP[j]=0.f;
    for (int j=i;j<NNODE;j+=st)     d_BOT[j]=0.f;
}

__global__ void kA_rel(const float* __restrict__ rela, const float* __restrict__ W1,
                       const float* __restrict__ b1v){
    __shared__ float s[128];
    int b=blockIdx.x, t=threadIdx.x;
    s[t]=rela[b*128+t];
    __syncthreads();
    float acc=b1v[t];
    #pragma unroll 8
    for(int i=0;i<128;i++) acc += s[i]*W1[i*128+t];
    d_TrelW1[b*128+t]=acc;
}

__global__ void kA_tim(const float* __restrict__ pe, const float* __restrict__ W1){
    __shared__ float s[32];
    int b=blockIdx.x, t=threadIdx.x;
    if(t<32) s[t]=pe[b*32+t];
    __syncthreads();
    float acc=0.f;
    #pragma unroll
    for(int i=0;i<32;i++) acc += s[i]*W1[(128+i)*128+t];
    d_TtimW1[b*128+t]=acc;
}

__global__ void kA_qr(const float* __restrict__ rela, const float* __restrict__ Wqr,
                      const int* __restrict__ q_rel, const float* __restrict__ bqr){
    __shared__ float s[128];
    int b=blockIdx.x, t=threadIdx.x;          // 64 threads
    int rel=q_rel[b];
    s[t]     = rela[rel*128+t];
    s[t+64]  = rela[rel*128+t+64];
    __syncthreads();
    float acc=bqr[t];
    #pragma unroll 8
    for(int i=0;i<128;i++) acc += s[i]*Wqr[i*64+t];
    d_Tqr[b*64+t]=acc;
}

__global__ __launch_bounds__(256) void kB(const float* __restrict__ hidden, const float* __restrict__ Ws){
    __shared__ float sW[128*64];
    __shared__ float sX[8][128];
    for(int i=threadIdx.x;i<128*64;i+=256) sW[i]=Ws[i];
    __syncthreads();
    int warp=threadIdx.x>>5, lane=threadIdx.x&31;
    int m0=lane*2;
    for(int n=blockIdx.x*8+warp; n<NNODE; n+=gridDim.x*8){
        *(float4*)&sX[warp][lane*4] = *(const float4*)&hidden[n*128+lane*4];
        __syncwarp();
        u64 acc=0ULL;
        #pragma unroll 16
        for(int j=0;j<128;j++){
            float v=sX[warp][j];
            u64 hvp=pk2(v,v);
            u64 w=*(const u64*)&sW[j*64+m0];
            fma2(acc,hvp,w);
        }
        float2 r; upk2(acc,r.x,r.y);
        *(float2*)&d_HSWS[n*64+m0]=r;
        __syncwarp();
    }
}

// ===================== mma.sync pair kernel =====================
#define SAS 136   // smem stride in bf16 elems (272B: ldmatrix bank-safe)
#define OFF_WR 34816
#define OFF_B2 52224
#define OFF_SA 52736
#define SMEM_C (OFF_SA+34816)

__device__ __forceinline__ void ldm4(u32&r0,u32&r1,u32&r2,u32&r3,u32 addr){
    asm volatile("ldmatrix.sync.aligned.m8n8.x4.shared.b16 {%0,%1,%2,%3},[%4];"
                 :"=r"(r0),"=r"(r1),"=r"(r2),"=r"(r3):"r"(addr));
}
__device__ __forceinline__ void mma16816(float* c, u32 a0,u32 a1,u32 a2,u32 a3, u32 b0,u32 b1){
    asm volatile("mma.sync.aligned.m16n8k16.row.col.f32.bf16.bf16.f32 "
        "{%0,%1,%2,%3},{%4,%5,%6,%7},{%8,%9},{%0,%1,%2,%3};"
        :"+f"(c[0]),"+f"(c[1]),"+f"(c[2]),"+f"(c[3])
        :"r"(a0),"r"(a1),"r"(a2),"r"(a3),"r"(b0),"r"(b1));
}
__device__ __forceinline__ void sts32(u32 addr, u32 v){ asm volatile("st.shared.b32 [%0],%1;"::"r"(addr),"r"(v):"memory"); }

__global__ __launch_bounds__(256) void kC_mma(const float* __restrict__ rela, const float* __restrict__ W2,
                                              const float* __restrict__ b2v, const float* __restrict__ Wr){
    extern __shared__ char smc[];
    __nv_bfloat16* sW2 = (__nv_bfloat16*)smc;
    __nv_bfloat16* sWr = (__nv_bfloat16*)(smc+OFF_WR);
    float* sB2 = (float*)(smc+OFF_B2);
    int tid=threadIdx.x, warp=tid>>5, lane=tid&31;

    {
        int n = tid & 127, kh = tid >> 7;
        for(int k=kh; k<128; k+=2) sW2[n*SAS+k] = __float2bfloat16(W2[k*128+n]);
        int n2 = tid & 63, kh2 = tid >> 6;
        for(int k=kh2; k<128; k+=4) sWr[n2*SAS+k] = __float2bfloat16(Wr[k*64+n2]);
        if(tid<128) sB2[tid] = b2v[tid];
    }
    __syncthreads();

    u32 sAb  = s2u(smc+OFF_SA) + warp*16*SAS*2;
    u32 sW2b = s2u(smc);
    u32 sWrb = s2u(smc+OFF_WR);

    u32 aAddr = sAb + (u32)(((lane&15)*SAS + (lane>>4)*8)*2);
    u32 bLpart = (u32)((((lane&7) + ((lane>>4)<<3))*SAS + ((lane>>3)&1)*8)*2);

    int rquad = lane>>2, lq = lane&3, cpair = lq*2;
    const int ngroup = (NPAIR+15)/16;

    for(int g=blockIdx.x*8+warp; g<ngroup; g+=gridDim.x*8){
        int pb = g*16;
        // ---- build A: h1 = lrelu(TrelW1+TtimW1+b1) bf16 ----
        #pragma unroll 4
        for(int rr=0; rr<16; rr++){
            int p = pb+rr; if(p>NPAIR-1) p=NPAIR-1;
            int rel=p/MAXH, tim=p-rel*MAXH;
            float4 a=*(const float4*)&d_TrelW1[rel*128+lane*4];
            float4 b=*(const float4*)&d_TtimW1[tim*128+lane*4];
            u32 lo=bf2(lrelu(a.x+b.x),lrelu(a.y+b.y));
            u32 hi=bf2(lrelu(a.z+b.z),lrelu(a.w+b.w));
            asm volatile("st.shared.v2.b32 [%0],{%1,%2};"
                         ::"r"(sAb+(u32)((rr*SAS+lane*4)*2)),"r"(lo),"r"(hi):"memory");
        }
        __syncwarp();
        // ---- GEMM1 ----
        float c[16][4];
        #pragma unroll
        for(int i=0;i<16;i++){ c[i][0]=0.f;c[i][1]=0.f;c[i][2]=0.f;c[i][3]=0.f; }
        #pragma unroll
        for(int kk=0;kk<8;kk++){
            u32 a0,a1,a2,a3;
            ldm4(a0,a1,a2,a3, aAddr + kk*32);
            #pragma unroll
            for(int np=0;np<8;np++){
                u32 b0,b1,b2r,b3;
                ldm4(b0,b1,b2r,b3, sW2b + bLpart + (u32)(np*16*SAS*2) + kk*32);
                mma16816(c[np*2],   a0,a1,a2,a3, b0,b1);
                mma16816(c[np*2+1], a0,a1,a2,a3, b2r,b3);
            }
        }
        // ---- epilogue1: hr -> d_HRh (bf16) + sA (bf16) ----
        {
            int p_a = pb + rquad, p_b = p_a + 8;
            int pac = p_a>NPAIR-1?NPAIR-1:p_a, pbc = p_b>NPAIR-1?NPAIR-1:p_b;
            const float* ra = rela + (pac/MAXH)*128;
            const float* rb = rela + (pbc/MAXH)*128;
            bool wa = p_a<NPAIR, wb = p_b<NPAIR;
            #pragma unroll
            for(int nt=0;nt<16;nt++){
                int col = nt*8 + cpair;
                float h0 = lrelu(c[nt][0]+sB2[col])   + __ldg(&ra[col]);
                float h1 = lrelu(c[nt][1]+sB2[col+1]) + __ldg(&ra[col+1]);
                float h2 = lrelu(c[nt][2]+sB2[col])   + __ldg(&rb[col]);
                float h3 = lrelu(c[nt][3]+sB2[col+1]) + __ldg(&rb[col+1]);
                u32 va = bf2(h0,h1), vb = bf2(h2,h3);
                if(wa) d_HRh[(size_t)p_a*64 + nt*4 + lq] = va;
                if(wb) d_HRh[(size_t)p_b*64 + nt*4 + lq] = vb;
                sts32(sAb+(u32)((rquad*SAS+col)*2),     va);
                sts32(sAb+(u32)(((rquad+8)*SAS+col)*2), vb);
            }
        }
        __syncwarp();
        // ---- GEMM2 ----
        float c2[8][4];
        #pragma unroll
        for(int i=0;i<8;i++){ c2[i][0]=0.f;c2[i][1]=0.f;c2[i][2]=0.f;c2[i][3]=0.f; }
        #pragma unroll
        for(int kk=0;kk<8;kk++){
            u32 a0,a1,a2,a3;
            ldm4(a0,a1,a2,a3, aAddr + kk*32);
            #pragma unroll
            for(int np=0;np<4;np++){
                u32 b0,b1,b2r,b3;
                ldm4(b0,b1,b2r,b3, sWrb + bLpart + (u32)(np*16*SAS*2) + kk*32);
                mma16816(c2[np*2],   a0,a1,a2,a3, b0,b1);
                mma16816(c2[np*2+1], a0,a1,a2,a3, b2r,b3);
            }
        }
        // ---- epilogue2: GA bf16 ----
        {
            int p_a = pb + rquad, p_b = p_a + 8;
            bool wa = p_a<NPAIR, wb = p_b<NPAIR;
            #pragma unroll
            for(int nt=0;nt<8;nt++){
                if(wa) d_GAh[(size_t)p_a*32 + nt*4 + lq] = bf2(c2[nt][0],c2[nt][1]);
                if(wb) d_GAh[(size_t)p_b*32 + nt*4 + lq] = bf2(c2[nt][2],c2[nt][3]);
            }
        }
        __syncwarp();
    }
}

// ===================== per-edge kernel =====================
__global__ __launch_bounds__(256) void kD(const int* __restrict__ edges, const float* __restrict__ hidden,
                                          const float* __restrict__ w_alpha, int nedge){
    int e_id=(blockIdx.x*blockDim.x+threadIdx.x)>>5;
    int lane=threadIdx.x&31;
    if(e_id>=nedge) return;
    const int* e = edges + (size_t)e_id*7;
    int r_idx=__ldg(e+0), rel=__ldg(e+2), sub=__ldg(e+4), obj=__ldg(e+5), tim=__ldg(e+6);
    int p = rel*MAXH + tim;
    int m0=lane*2;
    float2 g1=*(const float2*)&d_HSWS[(size_t)sub*64+m0];
    float2 g2=bf2f(__ldg(&d_GAh[(size_t)p*32+lane]));
    float2 g3=*(const float2*)&d_Tqr[r_idx*64+m0];
    float wa0=__ldg(&w_alpha[m0]), wa1=__ldg(&w_alpha[m0+1]);
    float s = lrelu(g1.x+g2.x+g3.x)*wa0 + lrelu(g1.y+g2.y+g3.y)*wa1;
    #pragma unroll
    for(int o=16;o;o>>=1) s += __shfl_xor_sync(0xffffffffu,s,o);
    float ea=expf(s);
    float4 hs=*(const float4*)&hidden[(size_t)sub*128+lane*4];
    uint2 hrb= *(const uint2*)&d_HRh[(size_t)p*64+lane*2];
    float2 r01=bf2f(hrb.x), r23=bf2f(hrb.y);
    float4 m;
    m.x=ea*(hs.x+r01.x); m.y=ea*(hs.y+r01.y);
    m.z=ea*(hs.z+r23.x); m.w=ea*(hs.w+r23.y);
    float* up=&d_UP[(size_t)obj*128+lane*4];
    asm volatile("red.global.add.v4.f32 [%0], {%1,%2,%3,%4};"
                 :: "l"(up),"f"(m.x),"f"(m.y),"f"(m.z),"f"(m.w) : "memory");
    if(lane==0) atomicAdd(&d_BOT[obj], ea);
}

// ===================== final GEMM =====================
__global__ __launch_bounds__(256) void kE(const float* __restrict__ Wh, float* __restrict__ out){
    extern __shared__ float sm[];
    float* sW=sm; float* sX=sm+128*128;
    for(int i=threadIdx.x;i<128*128;i+=256) sW[i]=Wh[i];
    __syncthreads();
    int warp=threadIdx.x>>5, lane=threadIdx.x&31;
    float* x=sX+warp*128;
    int k0=lane*4;
    for(int n=blockIdx.x*8+warp; n<NNODE; n+=gridDim.x*8){
        float inv=1.f/(d_BOT[n]+1e-5f);
        float4 u=*(const float4*)&d_UP[(size_t)n*128+k0];
        float4 xx; xx.x=u.x*inv; xx.y=u.y*inv; xx.z=u.z*inv; xx.w=u.w*inv;
        *(float4*)&x[k0]=xx;
        __syncwarp();
        u64 a01=0ULL, a23=0ULL;
        #pragma unroll 16
        for(int j=0;j<128;j++){
            float v=x[j];
            u64 hv=pk2(v,v);
            ulonglong2 w=*(const ulonglong2*)&sW[j*128+k0];
            fma2(a01,hv,w.x); fma2(a23,hv,w.y);
        }
        float4 r; upk2(a01,r.x,r.y); upk2(a23,r.z,r.w);
        *(float4*)&out[(size_t)n*128+k0]=r;
        __syncwarp();
    }
}

extern "C" void kernel_launch(void* const* d_in, const int* in_sizes, int n_in,
                              void* d_out, int out_size){
    const float* hidden =(const float*)d_in[0];
    const float* rela   =(const float*)d_in[1];
    const float* pe     =(const float*)d_in[2];
    const float* W1     =(const float*)d_in[3];
    const float* b1     =(const float*)d_in[4];
    const float* W2     =(const float*)d_in[5];
    const float* b2     =(const float*)d_in[6];
    const float* Ws     =(const float*)d_in[7];
    const float* Wr     =(const float*)d_in[8];
    const float* Wqr    =(const float*)d_in[9];
    const float* bqr    =(const float*)d_in[10];
    const float* w_alpha=(const float*)d_in[11];
    const float* Wh     =(const float*)d_in[12];
    const int*   q_rel  =(const int*)d_in[13];
    const int*   edges  =(const int*)d_in[14];
    float* out=(float*)d_out;
    int nedge = in_sizes[14]/7;

    int smemE = (128*128 + 8*128)*(int)sizeof(float);
    cudaFuncSetAttribute(kC_mma, cudaFuncAttributeMaxDynamicSharedMemorySize, SMEM_C);
    cudaFuncSetAttribute(kE, cudaFuncAttributeMaxDynamicSharedMemorySize, smemE);

    kZero<<<512,256>>>();
    kA_rel<<<VOCAB,128>>>(rela,W1,b1);
    kA_tim<<<MAXH,128>>>(pe,W1);
    kA_qr<<<NQ,64>>>(rela,Wqr,q_rel,bqr);
    kB<<<296,256>>>(hidden,Ws);
    kC_mma<<<296,256,SMEM_C>>>(rela,W2,b2,Wr);
    kD<<<(nedge*32+255)/256,256>>>(edges,hidden,w_alpha,nedge);
    kE<<<296,256,smemE>>>(Wh,out);
}